// round 16
// baseline (speedup 1.0000x reference)
#include <cuda_runtime.h>
#include <cuda_fp16.h>
#include <math.h>
#include <stdint.h>

// ---------------------------------------------------------------------------
// B=8, H=W=128, NW=8, D=256.  M=131072 tokens, 512 windows x 256 x 256.
// R16: R14 base (BK=64, 2-stage) + compile-time K (full mainloop unroll) +
// hoisted gather indices.  Dual configs: 128x128/256thr 2 CTAs/SM (QKV+FFN1);
// 128x256/512thr LN-fused (fc, FFN2); fused flash attention.
// ---------------------------------------------------------------------------
#define M_TOK 131072
#define WIN   65536
#define BUFE  33554432ULL
#define QKV_STRIDE 768
#define LOG2E 1.44269504088896f

__device__ __half g_in0h[BUFE];
__device__ __half g_in1h[BUFE];
__device__ __half g_qkv[100663296ULL];          // [131072][768] Q|K|V
__device__ __half g_awh[BUFE];
__device__ __half g_xbh[BUFE];
__device__ __half g_ah[BUFE];
__device__ __half g_hh[268435456ULL];
__device__ float  g_f0f[BUFE];
__device__ __half g_wTh[8 * 65536];
__device__ __half g_w1h[2048 * 512];
__device__ __half g_w2h[256 * 2048];

// ---------------------------------------------------------------------------
__device__ __forceinline__ uint32_t smem_u32(const void* p) {
    uint32_t a;
    asm("{ .reg .u64 t; cvta.to.shared.u64 t, %1; cvt.u32.u64 %0, t; }" : "=r"(a) : "l"(p));
    return a;
}
__device__ __forceinline__ void cp16(uint32_t s, const void* g) {
    asm volatile("cp.async.cg.shared.global [%0], [%1], 16;" :: "r"(s), "l"(g));
}
#define CP_COMMIT() asm volatile("cp.async.commit_group;" ::: "memory")
#define CP_WAIT1()  asm volatile("cp.async.wait_group 1;" ::: "memory")
#define CP_WAIT0()  asm volatile("cp.async.wait_group 0;" ::: "memory")

#define LDSM4(r, a) asm volatile( \
    "ldmatrix.sync.aligned.m8n8.x4.shared.b16 {%0,%1,%2,%3}, [%4];" \
    : "=r"((r)[0]), "=r"((r)[1]), "=r"((r)[2]), "=r"((r)[3]) : "r"(a))
#define LDSM4T(r, a) asm volatile( \
    "ldmatrix.sync.aligned.m8n8.x4.trans.shared.b16 {%0,%1,%2,%3}, [%4];" \
    : "=r"((r)[0]), "=r"((r)[1]), "=r"((r)[2]), "=r"((r)[3]) : "r"(a))

#define MMA2(c, a, b0, b1) asm volatile( \
    "mma.sync.aligned.m16n8k16.row.col.f32.f16.f16.f32 " \
    "{%0,%1,%2,%3},{%4,%5,%6,%7},{%8,%9},{%0,%1,%2,%3};" \
    : "+f"((c)[0]), "+f"((c)[1]), "+f"((c)[2]), "+f"((c)[3]) \
    : "r"((a)[0]), "r"((a)[1]), "r"((a)[2]), "r"((a)[3]), "r"(b0), "r"(b1))

__device__ __forceinline__ float ex2f(float x) {
    float r;
    asm("ex2.approx.ftz.f32 %0, %1;" : "=f"(r) : "f"(x));
    return r;
}

// Window permutations (verified R1)
__device__ __forceinline__ int w2t(int r) {
    int w = r >> 8, n = r & 255;
    int b = w >> 6, wy = (w >> 3) & 7, wx = w & 7;
    int h = (wy * 16 + (n >> 4) + 8) & 127;
    int c = (wx * 16 + (n & 15) + 8) & 127;
    return (b << 14) | (h << 7) | c;
}
__device__ __forceinline__ int t2w(int t) {
    int b = t >> 14, rem = t & 16383;
    int h = rem >> 7, c = rem & 127;
    int h2 = (h - 8) & 127, c2 = (c - 8) & 127;
    return (((b << 6) | ((h2 >> 4) << 3) | (c2 >> 4)) << 8) | ((h2 & 15) << 4) | (c2 & 15);
}

// ---------------------------------------------------------------------------
// SMALL GEMM: CTA 128x128, 256 thr, 8 warps (4M x 2N), warp 32x64, BK=64,
// 2-stage, 2 CTAs/SM.  NC = K/64 compile-time.
// AMODE: 3 concat(Ah|A2h), 4 gather + A select.  EPI: 1 pack, 3 gelu.
// ---------------------------------------------------------------------------
template<int AMODE, int EPI, int NC>
__global__ void __launch_bounds__(256, 2)
mma_gemm_s(const __half* __restrict__ Ah, const __half* __restrict__ A2h,
           const __half* __restrict__ Bh,
           __half* __restrict__ Ch, int Nld)
{
    constexpr int K = NC * 64;
    constexpr int APL = 128 * 72;
    constexpr int BPL = 128 * 72;
    constexpr int STG = APL + BPL;

    extern __shared__ __align__(16) char smraw[];
    __half* sm = (__half*)smraw;
    const uint32_t smb = smem_u32(smraw);

    const int tid = threadIdx.x, lane = tid & 31, warp = tid >> 5;
    const int mw = warp >> 1, nw = warp & 1;
    const int m0 = blockIdx.y * 128, n0 = blockIdx.x * 128;

    // Hoisted A-gather rows (same 4 rows each stage)
    int arow[4];
#pragma unroll
    for (int it = 0; it < 4; ++it) {
        int seg = it * 256 + tid;
        int r = seg >> 3;
        int gr = m0 + r;
        arow[it] = (AMODE == 4) ? w2t(gr) : gr;
    }

    auto load_stage = [&](int s, int c) {
        const int k0 = c << 6;
        __half* As = sm + s * STG;
        __half* Bs = As + APL;
        const __half* ash = Ah;
        int kc = k0;
        constexpr int rlen = (AMODE == 3 || AMODE == 4) ? 256 : K;
        if (AMODE == 3) {
            if (k0 >= 256) { ash = A2h; kc = k0 - 256; }
        }
        if (AMODE == 4) {
            if (n0 >= 256) ash = A2h;
        }
#pragma unroll
        for (int it = 0; it < 4; ++it) {
            int seg = it * 256 + tid;
            int r = seg >> 3, cs = (seg & 7) << 3;
            cp16(smem_u32(As + r * 72 + cs), ash + (size_t)arow[it] * rlen + kc + cs);
        }
#pragma unroll
        for (int it = 0; it < 4; ++it) {
            int seg = it * 256 + tid;
            int r = seg >> 3, cs = (seg & 7) << 3;
            cp16(smem_u32(Bs + r * 72 + cs), Bh + (size_t)(n0 + r) * K + k0 + cs);
        }
    };

    float acc[2][8][4];
#pragma unroll
    for (int i = 0; i < 2; i++)
#pragma unroll
        for (int j = 0; j < 8; j++)
#pragma unroll
            for (int e = 0; e < 4; e++) acc[i][j][e] = 0.f;

    load_stage(0, 0); CP_COMMIT();

#pragma unroll
    for (int cc = 0; cc < NC; ++cc) {
        if (cc + 1 < NC) { load_stage((cc + 1) & 1, cc + 1); CP_COMMIT(); CP_WAIT1(); }
        else CP_WAIT0();
        __syncthreads();

        const uint32_t sA = smb + ((cc & 1) * STG) * 2;
        const uint32_t sB = sA + APL * 2;

#pragma unroll
        for (int kk = 0; kk < 64; kk += 16) {
            uint32_t aH[2][4];
#pragma unroll
            for (int i = 0; i < 2; i++) {
                uint32_t ad = sA + (((mw * 32 + i * 16 + (lane & 15)) * 72 + kk + ((lane >> 4) << 3)) << 1);
                LDSM4(aH[i], ad);
            }
#pragma unroll
            for (int jg = 0; jg < 2; jg++) {
                uint32_t bH[2][4];
#pragma unroll
                for (int jp = 0; jp < 2; jp++) {
                    int nb = nw * 64 + (jg * 2 + jp) * 16;
                    int row = nb + (lane & 7) + ((lane >> 4) & 1) * 8;
                    int col = kk + ((lane >> 3) & 1) * 8;
                    LDSM4(bH[jp], sB + ((row * 72 + col) << 1));
                }
#pragma unroll
                for (int i = 0; i < 2; i++)
#pragma unroll
                    for (int jp = 0; jp < 2; jp++) {
                        MMA2(acc[i][jg * 4 + jp * 2 + 0], aH[i], bH[jp][0], bH[jp][1]);
                        MMA2(acc[i][jg * 4 + jp * 2 + 1], aH[i], bH[jp][2], bH[jp][3]);
                    }
            }
        }
        __syncthreads();
    }

    const int lr4 = lane >> 2;
    const int lc2 = (lane & 3) * 2;

#pragma unroll
    for (int i = 0; i < 2; i++) {
#pragma unroll
        for (int half = 0; half < 2; half++) {
            int gr = m0 + mw * 32 + i * 16 + half * 8 + lr4;
            __half* ch = Ch + (size_t)gr * Nld;
#pragma unroll
            for (int j = 0; j < 8; j++) {
                int c = n0 + nw * 64 + j * 8 + lc2;
                float v0 = acc[i][j][half * 2 + 0];
                float v1 = acc[i][j][half * 2 + 1];
                if (EPI == 3) {
                    v0 = 0.5f * v0 * (1.f + erff(v0 * 0.70710678118654752f));
                    v1 = 0.5f * v1 * (1.f + erff(v1 * 0.70710678118654752f));
                }
                *(__half2*)(ch + c) = __halves2half2(__float2half(v0), __float2half(v1));
            }
        }
    }
}

// ---------------------------------------------------------------------------
// BIG GEMM: CTA 128x256, 512 thr, 16 warps (4M x 4N), warp 32x64, BK=64,
// 2-stage.  LN epilogues.  NC compile-time.
// AMODE: 0 direct, 2 inv-gather.  EPI: 4 LN+res->f32+hi, 5 LN->hi, 6 LN+res->f32
// ---------------------------------------------------------------------------
template<int AMODE, int EPI, int NC>
__global__ void __launch_bounds__(512, 1)
mma_gemm(const __half* __restrict__ Ah, const __half* __restrict__ Bh,
         float* __restrict__ Cf, __half* __restrict__ Ch,
         const float* __restrict__ Res, const float* __restrict__ gw,
         const float* __restrict__ bw, int Nld)
{
    constexpr int K = NC * 64;
    constexpr int APL = 128 * 72;
    constexpr int BPL = 256 * 72;
    constexpr int STG = APL + BPL;

    extern __shared__ __align__(16) char smraw[];
    __shared__ float sred[2][128][4];
    __half* sm = (__half*)smraw;
    const uint32_t smb = smem_u32(smraw);

    const int tid = threadIdx.x, lane = tid & 31, warp = tid >> 5;
    const int mw = warp >> 2, nw = warp & 3;
    const int m0 = blockIdx.y * 128;

    int arow[2];
#pragma unroll
    for (int it = 0; it < 2; ++it) {
        int seg = it * 512 + tid;
        int r = seg >> 3;
        int gr = m0 + r;
        arow[it] = (AMODE == 2) ? t2w(gr) : gr;
    }

    auto load_stage = [&](int s, int c) {
        const int k0 = c << 6;
        __half* As = sm + s * STG;
        __half* Bs = As + APL;
#pragma unroll
        for (int it = 0; it < 2; ++it) {
            int seg = it * 512 + tid;
            int r = seg >> 3, cs = (seg & 7) << 3;
            cp16(smem_u32(As + r * 72 + cs), Ah + (size_t)arow[it] * K + k0 + cs);
        }
#pragma unroll
        for (int it = 0; it < 4; ++it) {
            int seg = it * 512 + tid;
            int r = seg >> 3, cs = (seg & 7) << 3;
            cp16(smem_u32(Bs + r * 72 + cs), Bh + (size_t)r * K + k0 + cs);
        }
    };

    float acc[2][8][4];
#pragma unroll
    for (int i = 0; i < 2; i++)
#pragma unroll
        for (int j = 0; j < 8; j++)
#pragma unroll
            for (int e = 0; e < 4; e++) acc[i][j][e] = 0.f;

    load_stage(0, 0); CP_COMMIT();

#pragma unroll 4
    for (int cc = 0; cc < NC; ++cc) {
        if (cc + 1 < NC) { load_stage((cc + 1) & 1, cc + 1); CP_COMMIT(); CP_WAIT1(); }
        else CP_WAIT0();
        __syncthreads();

        const uint32_t sA = smb + ((cc & 1) * STG) * 2;
        const uint32_t sB = sA + APL * 2;

#pragma unroll
        for (int kk = 0; kk < 64; kk += 16) {
            uint32_t aH[2][4];
#pragma unroll
            for (int i = 0; i < 2; i++) {
                uint32_t ad = sA + (((mw * 32 + i * 16 + (lane & 15)) * 72 + kk + ((lane >> 4) << 3)) << 1);
                LDSM4(aH[i], ad);
            }
#pragma unroll
            for (int jg = 0; jg < 2; jg++) {
                uint32_t bH[2][4];
#pragma unroll
                for (int jp = 0; jp < 2; jp++) {
                    int nb = nw * 64 + (jg * 2 + jp) * 16;
                    int row = nb + (lane & 7) + ((lane >> 4) & 1) * 8;
                    int col = kk + ((lane >> 3) & 1) * 8;
                    LDSM4(bH[jp], sB + ((row * 72 + col) << 1));
                }
#pragma unroll
                for (int i = 0; i < 2; i++)
#pragma unroll
                    for (int jp = 0; jp < 2; jp++) {
                        MMA2(acc[i][jg * 4 + jp * 2 + 0], aH[i], bH[jp][0], bH[jp][1]);
                        MMA2(acc[i][jg * 4 + jp * 2 + 1], aH[i], bH[jp][2], bH[jp][3]);
                    }
            }
        }
        __syncthreads();
    }

    const int lr4 = lane >> 2;
    const int lc2 = (lane & 3) * 2;

#pragma unroll
    for (int i = 0; i < 2; i++)
#pragma unroll
        for (int half = 0; half < 2; half++) {
            int lr = mw * 32 + i * 16 + half * 8 + lr4;
            float s1 = 0.f, s2 = 0.f;
#pragma unroll
            for (int j = 0; j < 8; j++) {
                float v0 = acc[i][j][half * 2 + 0];
                float v1 = acc[i][j][half * 2 + 1];
                s1 += v0 + v1;
                s2 += v0 * v0 + v1 * v1;
            }
            s1 += __shfl_xor_sync(0xffffffffu, s1, 1);
            s1 += __shfl_xor_sync(0xffffffffu, s1, 2);
            s2 += __shfl_xor_sync(0xffffffffu, s2, 1);
            s2 += __shfl_xor_sync(0xffffffffu, s2, 2);
            if ((lane & 3) == 0) { sred[0][lr][nw] = s1; sred[1][lr][nw] = s2; }
        }
    __syncthreads();
#pragma unroll
    for (int i = 0; i < 2; i++)
#pragma unroll
        for (int half = 0; half < 2; half++) {
            int lr = mw * 32 + i * 16 + half * 8 + lr4;
            int gr = m0 + lr;
            float t1 = sred[0][lr][0] + sred[0][lr][1] + sred[0][lr][2] + sred[0][lr][3];
            float t2 = sred[1][lr][0] + sred[1][lr][1] + sred[1][lr][2] + sred[1][lr][3];
            float mean = t1 * (1.f / 256.f);
            float var = t2 * (1.f / 256.f) - mean * mean;
            float rstd = rsqrtf(var + 1e-5f);
#pragma unroll
            for (int j = 0; j < 8; j++) {
                int c = nw * 64 + j * 8 + lc2;
                float2 gv = *(const float2*)(gw + c);
                float2 bv = *(const float2*)(bw + c);
                float y0 = (acc[i][j][half * 2 + 0] - mean) * rstd * gv.x + bv.x;
                float y1 = (acc[i][j][half * 2 + 1] - mean) * rstd * gv.y + bv.y;
                if (EPI == 4 || EPI == 6) {
                    float2 rv = *(const float2*)(Res + (size_t)gr * 256 + c);
                    y0 += rv.x; y1 += rv.y;
                }
                if (EPI == 4 || EPI == 6)
                    *(float2*)(Cf + (size_t)gr * Nld + c) = make_float2(y0, y1);
                if (EPI == 4 || EPI == 5)
                    *(__half2*)(Ch + (size_t)gr * Nld + c) = __halves2half2(
                        __float2half(y0), __float2half(y1));
            }
        }
}

// ---------------------------------------------------------------------------
// Fused attention, QKV interleaved [row][768].  512 thr.
// QK: BK=64 2-stage.  V: BK=32 2-stage.
// ---------------------------------------------------------------------------
#define ATT_APL   (128 * 72)
#define ATT_STG   (128 * 72 + 256 * 72)
#define P_STRIDE  264
#define VOFF      (128 * P_STRIDE * 2)
#define VSTG      (32 * P_STRIDE * 2)
#define ATT_SMEM  (2 * ATT_STG * 2)              // 110592 B

__global__ void __launch_bounds__(512, 1)
attn_fused(const __half* __restrict__ qkv,
           __half* __restrict__ awh, const float* __restrict__ mask)
{
    extern __shared__ __align__(16) char smraw[];
    __shared__ float sred[2][128][4];
    __half* sm = (__half*)smraw;
    const uint32_t smb = smem_u32(smraw);

    const int tid = threadIdx.x, lane = tid & 31, warp = tid >> 5;
    const int mw = warp >> 2, nw = warp & 3;
    const int z = blockIdx.z;
    const int m0 = blockIdx.y * 128;

    const __half* base = qkv + (size_t)z * 256 * QKV_STRIDE;

    auto load_qk = [&](int s, int c) {
        const int k0 = c << 6;
        __half* As = sm + s * ATT_STG;
        __half* Bs = As + ATT_APL;
#pragma unroll
        for (int it = 0; it < 2; ++it) {
            int seg = it * 512 + tid;
            int r = seg >> 3, cs = (seg & 7) << 3;
            cp16(smem_u32(As + r * 72 + cs), base + (size_t)(m0 + r) * QKV_STRIDE + k0 + cs);
        }
#pragma unroll
        for (int it = 0; it < 4; ++it) {
            int seg = it * 512 + tid;
            int r = seg >> 3, cs = (seg & 7) << 3;
            cp16(smem_u32(Bs + r * 72 + cs), base + (size_t)r * QKV_STRIDE + 256 + k0 + cs);
        }
    };

    float acc[2][8][4];
#pragma unroll
    for (int i = 0; i < 2; i++)
#pragma unroll
        for (int j = 0; j < 8; j++)
#pragma unroll
            for (int e = 0; e < 4; e++) acc[i][j][e] = 0.f;

    load_qk(0, 0); CP_COMMIT();

#pragma unroll
    for (int cc = 0; cc < 4; ++cc) {
        if (cc + 1 < 4) { load_qk((cc + 1) & 1, cc + 1); CP_COMMIT(); CP_WAIT1(); }
        else CP_WAIT0();
        __syncthreads();

        const uint32_t sA = smb + ((cc & 1) * ATT_STG) * 2;
        const uint32_t sB = sA + ATT_APL * 2;

#pragma unroll
        for (int kk = 0; kk < 64; kk += 16) {
            uint32_t aH[2][4];
#pragma unroll
            for (int i = 0; i < 2; i++) {
                uint32_t ad = sA + (((mw * 32 + i * 16 + (lane & 15)) * 72 + kk + ((lane >> 4) << 3)) << 1);
                LDSM4(aH[i], ad);
            }
#pragma unroll
            for (int jg = 0; jg < 2; jg++) {
                uint32_t bH[2][4];
#pragma unroll
                for (int jp = 0; jp < 2; jp++) {
                    int nb = nw * 64 + (jg * 2 + jp) * 16;
                    int row = nb + (lane & 7) + ((lane >> 4) & 1) * 8;
                    int col = kk + ((lane >> 3) & 1) * 8;
                    LDSM4(bH[jp], sB + ((row * 72 + col) << 1));
                }
#pragma unroll
                for (int i = 0; i < 2; i++)
#pragma unroll
                    for (int jp = 0; jp < 2; jp++) {
                        MMA2(acc[i][jg * 4 + jp * 2 + 0], aH[i], bH[jp][0], bH[jp][1]);
                        MMA2(acc[i][jg * 4 + jp * 2 + 1], aH[i], bH[jp][2], bH[jp][3]);
                    }
            }
        }
        __syncthreads();
    }

    const int lr4 = lane >> 2;
    const int lc2 = (lane & 3) * 2;
    {
        const float SCL = 0.0625f * LOG2E;
        const float* mrow = mask + (size_t)(z & 63) * WIN;
#pragma unroll
        for (int i = 0; i < 2; i++)
#pragma unroll
            for (int half = 0; half < 2; half++) {
                int lr = mw * 32 + i * 16 + half * 8 + lr4;
                int grm = m0 + lr;
                float mx = -1e30f;
#pragma unroll
                for (int j = 0; j < 8; j++) {
                    int c = nw * 64 + j * 8 + lc2;
                    float2 mk = *(const float2*)(mrow + (size_t)grm * 256 + c);
                    float v0 = fmaf(acc[i][j][half * 2 + 0], SCL, mk.x * LOG2E);
                    float v1 = fmaf(acc[i][j][half * 2 + 1], SCL, mk.y * LOG2E);
                    acc[i][j][half * 2 + 0] = v0;
                    acc[i][j][half * 2 + 1] = v1;
                    mx = fmaxf(mx, fmaxf(v0, v1));
                }
                mx = fmaxf(mx, __shfl_xor_sync(0xffffffffu, mx, 1));
                mx = fmaxf(mx, __shfl_xor_sync(0xffffffffu, mx, 2));
                if ((lane & 3) == 0) sred[0][lr][nw] = mx;
            }
        __syncthreads();
#pragma unroll
        for (int i = 0; i < 2; i++)
#pragma unroll
            for (int half = 0; half < 2; half++) {
                int lr = mw * 32 + i * 16 + half * 8 + lr4;
                float mx = fmaxf(fmaxf(sred[0][lr][0], sred[0][lr][1]),
                                 fmaxf(sred[0][lr][2], sred[0][lr][3]));
                float sum = 0.f;
#pragma unroll
                for (int j = 0; j < 8; j++) {
                    float e0 = ex2f(acc[i][j][half * 2 + 0] - mx);
                    float e1 = ex2f(acc[i][j][half * 2 + 1] - mx);
                    acc[i][j][half * 2 + 0] = e0;
                    acc[i][j][half * 2 + 1] = e1;
                    sum += e0 + e1;
                }
                sum += __shfl_xor_sync(0xffffffffu, sum, 1);
                sum += __shfl_xor_sync(0xffffffffu, sum, 2);
                if ((lane & 3) == 0) sred[1][lr][nw] = sum;
            }
        __syncthreads();
#pragma unroll
        for (int i = 0; i < 2; i++)
#pragma unroll
            for (int half = 0; half < 2; half++) {
                int lr = mw * 32 + i * 16 + half * 8 + lr4;
                float tot = sred[1][lr][0] + sred[1][lr][1] + sred[1][lr][2] + sred[1][lr][3];
                float inv = 1.f / tot;
#pragma unroll
                for (int j = 0; j < 8; j++) {
                    int c = nw * 64 + j * 8 + lc2;
                    *(__half2*)(sm + lr * P_STRIDE + c) = __halves2half2(
                        __float2half(acc[i][j][half * 2 + 0] * inv),
                        __float2half(acc[i][j][half * 2 + 1] * inv));
                }
            }
    }
    __syncthreads();

    auto load_v = [&](int s, int c) {
        const int k0 = c << 5;
        const uint32_t vb = smb + VOFF + s * VSTG;
#pragma unroll
        for (int it = 0; it < 2; ++it) {
            int seg = it * 512 + tid;
            int r = seg >> 5, cs = (seg & 31) << 3;
            cp16(vb + ((r * P_STRIDE + cs) << 1),
                 base + (size_t)(k0 + r) * QKV_STRIDE + 512 + cs);
        }
    };

    float oacc[2][8][4];
#pragma unroll
    for (int i = 0; i < 2; i++)
#pragma unroll
        for (int j = 0; j < 8; j++)
#pragma unroll
            for (int e = 0; e < 4; e++) oacc[i][j][e] = 0.f;

    load_v(0, 0); CP_COMMIT();
    load_v(1, 1); CP_COMMIT();

#pragma unroll
    for (int c = 0; c < 8; ++c) {
        if (c < 7) { CP_WAIT1(); } else { CP_WAIT0(); }
        __syncthreads();

        const uint32_t sV = smb + VOFF + (c & 1) * VSTG;

#pragma unroll
        for (int kk = 0; kk < 32; kk += 16) {
            uint32_t aP[2][4];
#pragma unroll
            for (int i = 0; i < 2; i++) {
                int row = mw * 32 + i * 16 + (lane & 15);
                int col = c * 32 + kk + ((lane >> 4) << 3);
                LDSM4(aP[i], smb + ((row * P_STRIDE + col) << 1));
            }
#pragma unroll
            for (int jg = 0; jg < 2; jg++) {
                uint32_t bH[2][4];
#pragma unroll
                for (int jp = 0; jp < 2; jp++) {
                    int nb = nw * 64 + (jg * 2 + jp) * 16;
                    int row = kk + (lane & 7) + ((lane >> 3) & 1) * 8;
                    int col = nb + ((lane >> 4) & 1) * 8;
                    LDSM4T(bH[jp], sV + ((row * P_STRIDE + col) << 1));
                }
#pragma unroll
                for (int i = 0; i < 2; i++)
#pragma unroll
                    for (int jp = 0; jp < 2; jp++) {
                        MMA2(oacc[i][jg * 4 + jp * 2 + 0], aP[i], bH[jp][0], bH[jp][1]);
                        MMA2(oacc[i][jg * 4 + jp * 2 + 1], aP[i], bH[jp][2], bH[jp][3]);
                    }
            }
        }
        __syncthreads();
        if (c + 2 < 8) { load_v(c & 1, c + 2); CP_COMMIT(); }
    }

#pragma unroll
    for (int i = 0; i < 2; i++)
#pragma unroll
        for (int half = 0; half < 2; half++) {
            int gr = m0 + mw * 32 + i * 16 + half * 8 + lr4;
            __half* ch = awh + (size_t)z * WIN + (size_t)gr * 256;
#pragma unroll
            for (int j = 0; j < 8; j++) {
                int c = nw * 64 + j * 8 + lc2;
                *(__half2*)(ch + c) = __halves2half2(
                    __float2half(oacc[i][j][half * 2 + 0]),
                    __float2half(oacc[i][j][half * 2 + 1]));
            }
        }
}

// ---------------------------------------------------------------------------
// Packing — 3 launches.
// ---------------------------------------------------------------------------
struct WPtrs { const float* w[8]; };

__global__ void packT8_kernel(WPtrs ws, __half* __restrict__ oh) {
    const float* W = ws.w[blockIdx.z];
    __half* o_h = oh + (size_t)blockIdx.z * 65536;
    for (int i = blockIdx.x * 256 + threadIdx.x; i < 65536; i += gridDim.x * 256) {
        int n = i >> 8, k = i & 255;
        o_h[i] = __float2half(W[k * 256 + n]);
    }
}

__global__ void packW2_kernel(const float* __restrict__ w1, const float* __restrict__ w2,
                              __half* __restrict__ o1, __half* __restrict__ o2) {
    const float* W = blockIdx.z ? w2 : w1;
    __half* O = blockIdx.z ? o2 : o1;
    int K = blockIdx.z ? 2048 : 512;
    int N = blockIdx.z ? 256 : 2048;
    size_t total = (size_t)K * N;
    for (size_t i = (size_t)blockIdx.x * blockDim.x + threadIdx.x; i < total;
         i += (size_t)gridDim.x * blockDim.x) {
        size_t n = i / K, k = i % K;
        O[i] = __float2half(W[k * (size_t)N + n]);
    }
}

__global__ void packh2_kernel(const float* __restrict__ x0, const float* __restrict__ x1,
                              __half* __restrict__ y0, __half* __restrict__ y1) {
    const float* x = blockIdx.z ? x1 : x0;
    __half* y = blockIdx.z ? y1 : y0;
    size_t i = ((size_t)blockIdx.x * 256 + threadIdx.x) * 4;
    float4 v = *(const float4*)(x + i);
    *(__half2*)(y + i) = __halves2half2(__float2half(v.x), __float2half(v.y));
    *(__half2*)(y + i + 2) = __halves2half2(__float2half(v.z), __float2half(v.w));
}

// ---------------------------------------------------------------------------
#define SM_GEMM  (2 * (128 * 72 + 256 * 72) * 2)   // 110592 B (big)
#define SM_GEMMS (2 * (128 * 72 + 128 * 72) * 2)   // 73728 B  (small, 2 CTAs/SM)

static bool g_attr = false;
static void set_attrs() {
    if (g_attr) return;
    cudaFuncSetAttribute(mma_gemm_s<4, 1, 4>, cudaFuncAttributeMaxDynamicSharedMemorySize, SM_GEMMS);
    cudaFuncSetAttribute(mma_gemm_s<3, 3, 8>, cudaFuncAttributeMaxDynamicSharedMemorySize, SM_GEMMS);
    cudaFuncSetAttribute(mma_gemm<2, 4, 4>, cudaFuncAttributeMaxDynamicSharedMemorySize, SM_GEMM);
    cudaFuncSetAttribute(mma_gemm<2, 5, 4>, cudaFuncAttributeMaxDynamicSharedMemorySize, SM_GEMM);
    cudaFuncSetAttribute(mma_gemm<0, 6, 32>, cudaFuncAttributeMaxDynamicSharedMemorySize, SM_GEMM);
    cudaFuncSetAttribute(attn_fused, cudaFuncAttributeMaxDynamicSharedMemorySize, ATT_SMEM);
    g_attr = true;
}

extern "C" void kernel_launch(void* const* d_in, const int* in_sizes, int n_in,
                              void* d_out, int out_size)
{
    set_attrs();

    const float* feat0 = (const float*)d_in[0];
    const float* feat1 = (const float*)d_in[1];
    const float* mask  = (const float*)d_in[2];
    const float* i_wq  = (const float*)d_in[6];
    const float* i_wk  = (const float*)d_in[7];
    const float* i_wv  = (const float*)d_in[8];
    const float* i_wfc = (const float*)d_in[9];
    const float* i_g   = (const float*)d_in[10];
    const float* i_b   = (const float*)d_in[11];
    const float* e_wq  = (const float*)d_in[12];
    const float* e_wk  = (const float*)d_in[13];
    const float* e_wv  = (const float*)d_in[14];
    const float* e_wfc = (const float*)d_in[15];
    const float* e_g   = (const float*)d_in[16];
    const float* e_b   = (const float*)d_in[17];
    const float* w1    = (const float*)d_in[18];
    const float* w2    = (const float*)d_in[19];
    const float* fg    = (const float*)d_in[20];
    const float* fb    = (const float*)d_in[21];
    float* out = (float*)d_out;

    __half *in0h, *in1h, *qkv, *awh, *xbh, *ah, *hh, *wTh, *w1h, *w2h;
    float *f0f;
    cudaGetSymbolAddress((void**)&in0h, g_in0h);
    cudaGetSymbolAddress((void**)&in1h, g_in1h);
    cudaGetSymbolAddress((void**)&qkv, g_qkv);
    cudaGetSymbolAddress((void**)&awh, g_awh);
    cudaGetSymbolAddress((void**)&xbh, g_xbh);
    cudaGetSymbolAddress((void**)&ah, g_ah);
    cudaGetSymbolAddress((void**)&hh, g_hh);
    cudaGetSymbolAddress((void**)&wTh, g_wTh);
    cudaGetSymbolAddress((void**)&w1h, g_w1h);
    cudaGetSymbolAddress((void**)&w2h, g_w2h);
    cudaGetSymbolAddress((void**)&f0f, g_f0f);

    const dim3 blk512(512);
    const dim3 blk256(256);
    const dim3 gproj(1, 1024, 1);
    const dim3 gqkv(6, 1024, 1);
    const dim3 gattn(1, 2, 512);
    const dim3 gffn1(16, 1024, 1);

    // ---- packing (3 launches) ----
    WPtrs wp;
    wp.w[0] = i_wq; wp.w[1] = i_wk; wp.w[2] = i_wv; wp.w[3] = i_wfc;
    wp.w[4] = e_wq; wp.w[5] = e_wk; wp.w[6] = e_wv; wp.w[7] = e_wfc;
    packT8_kernel<<<dim3(32, 1, 8), blk256>>>(wp, wTh);
    packW2_kernel<<<dim3(512, 1, 2), blk256>>>(w1, w2, w1h, w2h);
    packh2_kernel<<<dim3(32768, 1, 2), blk256>>>(feat0, feat1, in0h, in1h);

    // ======== Block 1 (intra) ========
    mma_gemm_s<4, 1, 4><<<gqkv, blk256, SM_GEMMS>>>(in0h, in0h, wTh + 0 * 65536,
        qkv, QKV_STRIDE);
    attn_fused<<<gattn, blk512, ATT_SMEM>>>(qkv, awh, mask);
    mma_gemm<2, 4, 4><<<gproj, blk512, SM_GEMM>>>(awh, wTh + 3 * 65536,
        f0f, xbh, feat0, i_g, i_b, 256);

    // ======== Block 2 (inter) ========
    mma_gemm_s<4, 1, 4><<<gqkv, blk256, SM_GEMMS>>>(xbh, in1h, wTh + 4 * 65536,
        qkv, QKV_STRIDE);
    attn_fused<<<gattn, blk512, ATT_SMEM>>>(qkv, awh, mask);
    mma_gemm<2, 5, 4><<<gproj, blk512, SM_GEMM>>>(awh, wTh + 7 * 65536,
        nullptr, ah, nullptr, e_g, e_b, 256);

    // ======== FFN ========
    mma_gemm_s<3, 3, 8><<<gffn1, blk256, SM_GEMMS>>>(xbh, ah, w1h,
        hh, 2048);
    mma_gemm<0, 6, 32><<<gproj, blk512, SM_GEMM>>>(hh, w2h,
        out, nullptr, f0f, fg, fb, 256);
}

// round 17
// speedup vs baseline: 1.4468x; 1.4468x over previous
#include <cuda_runtime.h>
#include <cuda_fp16.h>
#include <math.h>
#include <stdint.h>

// ---------------------------------------------------------------------------
// B=8, H=W=128, NW=8, D=256.  M=131072 tokens, 512 windows x 256 x 256.
// R17: R14 champion (BK=64, 2-stage, ROLLED chunk loop) + hoisted gather rows.
// Dual GEMM configs: 128x128/256thr 2 CTAs/SM (QKV+FFN1);
// 128x256/512thr LN-fused (fc, FFN2); fused flash attention.
// ---------------------------------------------------------------------------
#define M_TOK 131072
#define WIN   65536
#define BUFE  33554432ULL
#define QKV_STRIDE 768
#define LOG2E 1.44269504088896f

__device__ __half g_in0h[BUFE];
__device__ __half g_in1h[BUFE];
__device__ __half g_qkv[100663296ULL];          // [131072][768] Q|K|V
__device__ __half g_awh[BUFE];
__device__ __half g_xbh[BUFE];
__device__ __half g_ah[BUFE];
__device__ __half g_hh[268435456ULL];
__device__ float  g_f0f[BUFE];
__device__ __half g_wTh[8 * 65536];
__device__ __half g_w1h[2048 * 512];
__device__ __half g_w2h[256 * 2048];

// ---------------------------------------------------------------------------
__device__ __forceinline__ uint32_t smem_u32(const void* p) {
    uint32_t a;
    asm("{ .reg .u64 t; cvta.to.shared.u64 t, %1; cvt.u32.u64 %0, t; }" : "=r"(a) : "l"(p));
    return a;
}
__device__ __forceinline__ void cp16(uint32_t s, const void* g) {
    asm volatile("cp.async.cg.shared.global [%0], [%1], 16;" :: "r"(s), "l"(g));
}
#define CP_COMMIT() asm volatile("cp.async.commit_group;" ::: "memory")
#define CP_WAIT1()  asm volatile("cp.async.wait_group 1;" ::: "memory")
#define CP_WAIT0()  asm volatile("cp.async.wait_group 0;" ::: "memory")

#define LDSM4(r, a) asm volatile( \
    "ldmatrix.sync.aligned.m8n8.x4.shared.b16 {%0,%1,%2,%3}, [%4];" \
    : "=r"((r)[0]), "=r"((r)[1]), "=r"((r)[2]), "=r"((r)[3]) : "r"(a))
#define LDSM4T(r, a) asm volatile( \
    "ldmatrix.sync.aligned.m8n8.x4.trans.shared.b16 {%0,%1,%2,%3}, [%4];" \
    : "=r"((r)[0]), "=r"((r)[1]), "=r"((r)[2]), "=r"((r)[3]) : "r"(a))

#define MMA2(c, a, b0, b1) asm volatile( \
    "mma.sync.aligned.m16n8k16.row.col.f32.f16.f16.f32 " \
    "{%0,%1,%2,%3},{%4,%5,%6,%7},{%8,%9},{%0,%1,%2,%3};" \
    : "+f"((c)[0]), "+f"((c)[1]), "+f"((c)[2]), "+f"((c)[3]) \
    : "r"((a)[0]), "r"((a)[1]), "r"((a)[2]), "r"((a)[3]), "r"(b0), "r"(b1))

__device__ __forceinline__ float ex2f(float x) {
    float r;
    asm("ex2.approx.ftz.f32 %0, %1;" : "=f"(r) : "f"(x));
    return r;
}

// Window permutations (verified R1)
__device__ __forceinline__ int w2t(int r) {
    int w = r >> 8, n = r & 255;
    int b = w >> 6, wy = (w >> 3) & 7, wx = w & 7;
    int h = (wy * 16 + (n >> 4) + 8) & 127;
    int c = (wx * 16 + (n & 15) + 8) & 127;
    return (b << 14) | (h << 7) | c;
}
__device__ __forceinline__ int t2w(int t) {
    int b = t >> 14, rem = t & 16383;
    int h = rem >> 7, c = rem & 127;
    int h2 = (h - 8) & 127, c2 = (c - 8) & 127;
    return (((b << 6) | ((h2 >> 4) << 3) | (c2 >> 4)) << 8) | ((h2 & 15) << 4) | (c2 & 15);
}

// ---------------------------------------------------------------------------
// SMALL GEMM: CTA 128x128, 256 thr, 8 warps (4M x 2N), warp 32x64, BK=64,
// 2-stage, 2 CTAs/SM.  Rolled chunk loop (runtime K).
// AMODE: 3 concat(Ah|A2h), 4 gather + A select.  EPI: 1 pack, 3 gelu.
// ---------------------------------------------------------------------------
template<int AMODE, int EPI>
__global__ void __launch_bounds__(256, 2)
mma_gemm_s(const __half* __restrict__ Ah, const __half* __restrict__ A2h,
           const __half* __restrict__ Bh,
           __half* __restrict__ Ch, int K, int Nld)
{
    constexpr int APL = 128 * 72;
    constexpr int BPL = 128 * 72;
    constexpr int STG = APL + BPL;

    extern __shared__ __align__(16) char smraw[];
    __half* sm = (__half*)smraw;
    const uint32_t smb = smem_u32(smraw);

    const int tid = threadIdx.x, lane = tid & 31, warp = tid >> 5;
    const int mw = warp >> 1, nw = warp & 1;
    const int m0 = blockIdx.y * 128, n0 = blockIdx.x * 128;

    const int nc = K >> 6;

    // Hoisted A-gather rows (loop-invariant across stages)
    int arow[4];
#pragma unroll
    for (int it = 0; it < 4; ++it) {
        int gr = m0 + ((it * 256 + tid) >> 3);
        arow[it] = (AMODE == 4) ? w2t(gr) : gr;
    }

    auto load_stage = [&](int s, int c) {
        const int k0 = c << 6;
        __half* As = sm + s * STG;
        __half* Bs = As + APL;
        const __half* ash = Ah;
        int kc = k0, rlen = K;
        if (AMODE == 3) {
            rlen = 256;
            if (k0 >= 256) { ash = A2h; kc = k0 - 256; }
        }
        if (AMODE == 4) {
            rlen = 256;
            if (n0 >= 256) ash = A2h;
        }
#pragma unroll
        for (int it = 0; it < 4; ++it) {
            int seg = it * 256 + tid;
            int r = seg >> 3, cs = (seg & 7) << 3;
            cp16(smem_u32(As + r * 72 + cs), ash + (size_t)arow[it] * rlen + kc + cs);
        }
#pragma unroll
        for (int it = 0; it < 4; ++it) {
            int seg = it * 256 + tid;
            int r = seg >> 3, cs = (seg & 7) << 3;
            cp16(smem_u32(Bs + r * 72 + cs), Bh + (size_t)(n0 + r) * K + k0 + cs);
        }
    };

    float acc[2][8][4];
#pragma unroll
    for (int i = 0; i < 2; i++)
#pragma unroll
        for (int j = 0; j < 8; j++)
#pragma unroll
            for (int e = 0; e < 4; e++) acc[i][j][e] = 0.f;

    load_stage(0, 0); CP_COMMIT();

    for (int cc = 0; cc < nc; ++cc) {
        if (cc + 1 < nc) { load_stage((cc + 1) & 1, cc + 1); CP_COMMIT(); CP_WAIT1(); }
        else CP_WAIT0();
        __syncthreads();

        const uint32_t sA = smb + ((cc & 1) * STG) * 2;
        const uint32_t sB = sA + APL * 2;

#pragma unroll
        for (int kk = 0; kk < 64; kk += 16) {
            uint32_t aH[2][4];
#pragma unroll
            for (int i = 0; i < 2; i++) {
                uint32_t ad = sA + (((mw * 32 + i * 16 + (lane & 15)) * 72 + kk + ((lane >> 4) << 3)) << 1);
                LDSM4(aH[i], ad);
            }
#pragma unroll
            for (int jg = 0; jg < 2; jg++) {
                uint32_t bH[2][4];
#pragma unroll
                for (int jp = 0; jp < 2; jp++) {
                    int nb = nw * 64 + (jg * 2 + jp) * 16;
                    int row = nb + (lane & 7) + ((lane >> 4) & 1) * 8;
                    int col = kk + ((lane >> 3) & 1) * 8;
                    LDSM4(bH[jp], sB + ((row * 72 + col) << 1));
                }
#pragma unroll
                for (int i = 0; i < 2; i++)
#pragma unroll
                    for (int jp = 0; jp < 2; jp++) {
                        MMA2(acc[i][jg * 4 + jp * 2 + 0], aH[i], bH[jp][0], bH[jp][1]);
                        MMA2(acc[i][jg * 4 + jp * 2 + 1], aH[i], bH[jp][2], bH[jp][3]);
                    }
            }
        }
        __syncthreads();
    }

    const int lr4 = lane >> 2;
    const int lc2 = (lane & 3) * 2;

#pragma unroll
    for (int i = 0; i < 2; i++) {
#pragma unroll
        for (int half = 0; half < 2; half++) {
            int gr = m0 + mw * 32 + i * 16 + half * 8 + lr4;
            __half* ch = Ch + (size_t)gr * Nld;
#pragma unroll
            for (int j = 0; j < 8; j++) {
                int c = n0 + nw * 64 + j * 8 + lc2;
                float v0 = acc[i][j][half * 2 + 0];
                float v1 = acc[i][j][half * 2 + 1];
                if (EPI == 3) {
                    v0 = 0.5f * v0 * (1.f + erff(v0 * 0.70710678118654752f));
                    v1 = 0.5f * v1 * (1.f + erff(v1 * 0.70710678118654752f));
                }
                *(__half2*)(ch + c) = __halves2half2(__float2half(v0), __float2half(v1));
            }
        }
    }
}

// ---------------------------------------------------------------------------
// BIG GEMM: CTA 128x256, 512 thr, 16 warps (4M x 4N), warp 32x64, BK=64,
// 2-stage, rolled loop.  LN epilogues.  AMODE: 0 direct, 2 inv-gather.
// EPI: 4 LN+res->f32+hi, 5 LN->hi, 6 LN+res->f32
// ---------------------------------------------------------------------------
template<int AMODE, int EPI>
__global__ void __launch_bounds__(512, 1)
mma_gemm(const __half* __restrict__ Ah, const __half* __restrict__ Bh,
         float* __restrict__ Cf, __half* __restrict__ Ch,
         const float* __restrict__ Res, const float* __restrict__ gw,
         const float* __restrict__ bw,
         int K, int Nld)
{
    constexpr int APL = 128 * 72;
    constexpr int BPL = 256 * 72;
    constexpr int STG = APL + BPL;

    extern __shared__ __align__(16) char smraw[];
    __shared__ float sred[2][128][4];
    __half* sm = (__half*)smraw;
    const uint32_t smb = smem_u32(smraw);

    const int tid = threadIdx.x, lane = tid & 31, warp = tid >> 5;
    const int mw = warp >> 2, nw = warp & 3;
    const int m0 = blockIdx.y * 128;

    const int nc = K >> 6;

    int arow[2];
#pragma unroll
    for (int it = 0; it < 2; ++it) {
        int gr = m0 + ((it * 512 + tid) >> 3);
        arow[it] = (AMODE == 2) ? t2w(gr) : gr;
    }

    auto load_stage = [&](int s, int c) {
        const int k0 = c << 6;
        __half* As = sm + s * STG;
        __half* Bs = As + APL;
#pragma unroll
        for (int it = 0; it < 2; ++it) {
            int seg = it * 512 + tid;
            int r = seg >> 3, cs = (seg & 7) << 3;
            cp16(smem_u32(As + r * 72 + cs), Ah + (size_t)arow[it] * K + k0 + cs);
        }
#pragma unroll
        for (int it = 0; it < 4; ++it) {
            int seg = it * 512 + tid;
            int r = seg >> 3, cs = (seg & 7) << 3;
            cp16(smem_u32(Bs + r * 72 + cs), Bh + (size_t)r * K + k0 + cs);
        }
    };

    float acc[2][8][4];
#pragma unroll
    for (int i = 0; i < 2; i++)
#pragma unroll
        for (int j = 0; j < 8; j++)
#pragma unroll
            for (int e = 0; e < 4; e++) acc[i][j][e] = 0.f;

    load_stage(0, 0); CP_COMMIT();

    for (int cc = 0; cc < nc; ++cc) {
        if (cc + 1 < nc) { load_stage((cc + 1) & 1, cc + 1); CP_COMMIT(); CP_WAIT1(); }
        else CP_WAIT0();
        __syncthreads();

        const uint32_t sA = smb + ((cc & 1) * STG) * 2;
        const uint32_t sB = sA + APL * 2;

#pragma unroll
        for (int kk = 0; kk < 64; kk += 16) {
            uint32_t aH[2][4];
#pragma unroll
            for (int i = 0; i < 2; i++) {
                uint32_t ad = sA + (((mw * 32 + i * 16 + (lane & 15)) * 72 + kk + ((lane >> 4) << 3)) << 1);
                LDSM4(aH[i], ad);
            }
#pragma unroll
            for (int jg = 0; jg < 2; jg++) {
                uint32_t bH[2][4];
#pragma unroll
                for (int jp = 0; jp < 2; jp++) {
                    int nb = nw * 64 + (jg * 2 + jp) * 16;
                    int row = nb + (lane & 7) + ((lane >> 4) & 1) * 8;
                    int col = kk + ((lane >> 3) & 1) * 8;
                    LDSM4(bH[jp], sB + ((row * 72 + col) << 1));
                }
#pragma unroll
                for (int i = 0; i < 2; i++)
#pragma unroll
                    for (int jp = 0; jp < 2; jp++) {
                        MMA2(acc[i][jg * 4 + jp * 2 + 0], aH[i], bH[jp][0], bH[jp][1]);
                        MMA2(acc[i][jg * 4 + jp * 2 + 1], aH[i], bH[jp][2], bH[jp][3]);
                    }
            }
        }
        __syncthreads();
    }

    const int lr4 = lane >> 2;
    const int lc2 = (lane & 3) * 2;

#pragma unroll
    for (int i = 0; i < 2; i++)
#pragma unroll
        for (int half = 0; half < 2; half++) {
            int lr = mw * 32 + i * 16 + half * 8 + lr4;
            float s1 = 0.f, s2 = 0.f;
#pragma unroll
            for (int j = 0; j < 8; j++) {
                float v0 = acc[i][j][half * 2 + 0];
                float v1 = acc[i][j][half * 2 + 1];
                s1 += v0 + v1;
                s2 += v0 * v0 + v1 * v1;
            }
            s1 += __shfl_xor_sync(0xffffffffu, s1, 1);
            s1 += __shfl_xor_sync(0xffffffffu, s1, 2);
            s2 += __shfl_xor_sync(0xffffffffu, s2, 1);
            s2 += __shfl_xor_sync(0xffffffffu, s2, 2);
            if ((lane & 3) == 0) { sred[0][lr][nw] = s1; sred[1][lr][nw] = s2; }
        }
    __syncthreads();
#pragma unroll
    for (int i = 0; i < 2; i++)
#pragma unroll
        for (int half = 0; half < 2; half++) {
            int lr = mw * 32 + i * 16 + half * 8 + lr4;
            int gr = m0 + lr;
            float t1 = sred[0][lr][0] + sred[0][lr][1] + sred[0][lr][2] + sred[0][lr][3];
            float t2 = sred[1][lr][0] + sred[1][lr][1] + sred[1][lr][2] + sred[1][lr][3];
            float mean = t1 * (1.f / 256.f);
            float var = t2 * (1.f / 256.f) - mean * mean;
            float rstd = rsqrtf(var + 1e-5f);
#pragma unroll
            for (int j = 0; j < 8; j++) {
                int c = nw * 64 + j * 8 + lc2;
                float2 gv = *(const float2*)(gw + c);
                float2 bv = *(const float2*)(bw + c);
                float y0 = (acc[i][j][half * 2 + 0] - mean) * rstd * gv.x + bv.x;
                float y1 = (acc[i][j][half * 2 + 1] - mean) * rstd * gv.y + bv.y;
                if (EPI == 4 || EPI == 6) {
                    float2 rv = *(const float2*)(Res + (size_t)gr * 256 + c);
                    y0 += rv.x; y1 += rv.y;
                }
                if (EPI == 4 || EPI == 6)
                    *(float2*)(Cf + (size_t)gr * Nld + c) = make_float2(y0, y1);
                if (EPI == 4 || EPI == 5)
                    *(__half2*)(Ch + (size_t)gr * Nld + c) = __halves2half2(
                        __float2half(y0), __float2half(y1));
            }
        }
}

// ---------------------------------------------------------------------------
// Fused attention, QKV interleaved [row][768].  512 thr.
// QK: BK=64 2-stage.  V: BK=32 2-stage.
// ---------------------------------------------------------------------------
#define ATT_APL   (128 * 72)
#define ATT_STG   (128 * 72 + 256 * 72)          // halves (27648)
#define P_STRIDE  264
#define VOFF      (128 * P_STRIDE * 2)           // 67584 B
#define VSTG      (32 * P_STRIDE * 2)            // 16896 B
#define ATT_SMEM  (2 * ATT_STG * 2)              // 110592 B

__global__ void __launch_bounds__(512, 1)
attn_fused(const __half* __restrict__ qkv,
           __half* __restrict__ awh, const float* __restrict__ mask)
{
    extern __shared__ __align__(16) char smraw[];
    __shared__ float sred[2][128][4];
    __half* sm = (__half*)smraw;
    const uint32_t smb = smem_u32(smraw);

    const int tid = threadIdx.x, lane = tid & 31, warp = tid >> 5;
    const int mw = warp >> 2, nw = warp & 3;
    const int z = blockIdx.z;
    const int m0 = blockIdx.y * 128;

    const __half* base = qkv + (size_t)z * 256 * QKV_STRIDE;

    auto load_qk = [&](int s, int c) {
        const int k0 = c << 6;
        __half* As = sm + s * ATT_STG;
        __half* Bs = As + ATT_APL;
#pragma unroll
        for (int it = 0; it < 2; ++it) {
            int seg = it * 512 + tid;
            int r = seg >> 3, cs = (seg & 7) << 3;
            cp16(smem_u32(As + r * 72 + cs), base + (size_t)(m0 + r) * QKV_STRIDE + k0 + cs);
        }
#pragma unroll
        for (int it = 0; it < 4; ++it) {
            int seg = it * 512 + tid;
            int r = seg >> 3, cs = (seg & 7) << 3;
            cp16(smem_u32(Bs + r * 72 + cs), base + (size_t)r * QKV_STRIDE + 256 + k0 + cs);
        }
    };

    float acc[2][8][4];
#pragma unroll
    for (int i = 0; i < 2; i++)
#pragma unroll
        for (int j = 0; j < 8; j++)
#pragma unroll
            for (int e = 0; e < 4; e++) acc[i][j][e] = 0.f;

    load_qk(0, 0); CP_COMMIT();

    for (int cc = 0; cc < 4; ++cc) {
        if (cc + 1 < 4) { load_qk((cc + 1) & 1, cc + 1); CP_COMMIT(); CP_WAIT1(); }
        else CP_WAIT0();
        __syncthreads();

        const uint32_t sA = smb + ((cc & 1) * ATT_STG) * 2;
        const uint32_t sB = sA + ATT_APL * 2;

#pragma unroll
        for (int kk = 0; kk < 64; kk += 16) {
            uint32_t aH[2][4];
#pragma unroll
            for (int i = 0; i < 2; i++) {
                uint32_t ad = sA + (((mw * 32 + i * 16 + (lane & 15)) * 72 + kk + ((lane >> 4) << 3)) << 1);
                LDSM4(aH[i], ad);
            }
#pragma unroll
            for (int jg = 0; jg < 2; jg++) {
                uint32_t bH[2][4];
#pragma unroll
                for (int jp = 0; jp < 2; jp++) {
                    int nb = nw * 64 + (jg * 2 + jp) * 16;
                    int row = nb + (lane & 7) + ((lane >> 4) & 1) * 8;
                    int col = kk + ((lane >> 3) & 1) * 8;
                    LDSM4(bH[jp], sB + ((row * 72 + col) << 1));
                }
#pragma unroll
                for (int i = 0; i < 2; i++)
#pragma unroll
                    for (int jp = 0; jp < 2; jp++) {
                        MMA2(acc[i][jg * 4 + jp * 2 + 0], aH[i], bH[jp][0], bH[jp][1]);
                        MMA2(acc[i][jg * 4 + jp * 2 + 1], aH[i], bH[jp][2], bH[jp][3]);
                    }
            }
        }
        __syncthreads();
    }

    const int lr4 = lane >> 2;
    const int lc2 = (lane & 3) * 2;
    {
        const float SCL = 0.0625f * LOG2E;
        const float* mrow = mask + (size_t)(z & 63) * WIN;
#pragma unroll
        for (int i = 0; i < 2; i++)
#pragma unroll
            for (int half = 0; half < 2; half++) {
                int lr = mw * 32 + i * 16 + half * 8 + lr4;
                int grm = m0 + lr;
                float mx = -1e30f;
#pragma unroll
                for (int j = 0; j < 8; j++) {
                    int c = nw * 64 + j * 8 + lc2;
                    float2 mk = *(const float2*)(mrow + (size_t)grm * 256 + c);
                    float v0 = fmaf(acc[i][j][half * 2 + 0], SCL, mk.x * LOG2E);
                    float v1 = fmaf(acc[i][j][half * 2 + 1], SCL, mk.y * LOG2E);
                    acc[i][j][half * 2 + 0] = v0;
                    acc[i][j][half * 2 + 1] = v1;
                    mx = fmaxf(mx, fmaxf(v0, v1));
                }
                mx = fmaxf(mx, __shfl_xor_sync(0xffffffffu, mx, 1));
                mx = fmaxf(mx, __shfl_xor_sync(0xffffffffu, mx, 2));
                if ((lane & 3) == 0) sred[0][lr][nw] = mx;
            }
        __syncthreads();
#pragma unroll
        for (int i = 0; i < 2; i++)
#pragma unroll
            for (int half = 0; half < 2; half++) {
                int lr = mw * 32 + i * 16 + half * 8 + lr4;
                float mx = fmaxf(fmaxf(sred[0][lr][0], sred[0][lr][1]),
                                 fmaxf(sred[0][lr][2], sred[0][lr][3]));
                float sum = 0.f;
#pragma unroll
                for (int j = 0; j < 8; j++) {
                    float e0 = ex2f(acc[i][j][half * 2 + 0] - mx);
                    float e1 = ex2f(acc[i][j][half * 2 + 1] - mx);
                    acc[i][j][half * 2 + 0] = e0;
                    acc[i][j][half * 2 + 1] = e1;
                    sum += e0 + e1;
                }
                sum += __shfl_xor_sync(0xffffffffu, sum, 1);
                sum += __shfl_xor_sync(0xffffffffu, sum, 2);
                if ((lane & 3) == 0) sred[1][lr][nw] = sum;
            }
        __syncthreads();
#pragma unroll
        for (int i = 0; i < 2; i++)
#pragma unroll
            for (int half = 0; half < 2; half++) {
                int lr = mw * 32 + i * 16 + half * 8 + lr4;
                float tot = sred[1][lr][0] + sred[1][lr][1] + sred[1][lr][2] + sred[1][lr][3];
                float inv = 1.f / tot;
#pragma unroll
                for (int j = 0; j < 8; j++) {
                    int c = nw * 64 + j * 8 + lc2;
                    *(__half2*)(sm + lr * P_STRIDE + c) = __halves2half2(
                        __float2half(acc[i][j][half * 2 + 0] * inv),
                        __float2half(acc[i][j][half * 2 + 1] * inv));
                }
            }
    }
    __syncthreads();

    auto load_v = [&](int s, int c) {
        const int k0 = c << 5;
        const uint32_t vb = smb + VOFF + s * VSTG;
#pragma unroll
        for (int it = 0; it < 2; ++it) {
            int seg = it * 512 + tid;
            int r = seg >> 5, cs = (seg & 31) << 3;
            cp16(vb + ((r * P_STRIDE + cs) << 1),
                 base + (size_t)(k0 + r) * QKV_STRIDE + 512 + cs);
        }
    };

    float oacc[2][8][4];
#pragma unroll
    for (int i = 0; i < 2; i++)
#pragma unroll
        for (int j = 0; j < 8; j++)
#pragma unroll
            for (int e = 0; e < 4; e++) oacc[i][j][e] = 0.f;

    load_v(0, 0); CP_COMMIT();
    load_v(1, 1); CP_COMMIT();

#pragma unroll
    for (int c = 0; c < 8; ++c) {
        if (c < 7) { CP_WAIT1(); } else { CP_WAIT0(); }
        __syncthreads();

        const uint32_t sV = smb + VOFF + (c & 1) * VSTG;

#pragma unroll
        for (int kk = 0; kk < 32; kk += 16) {
            uint32_t aP[2][4];
#pragma unroll
            for (int i = 0; i < 2; i++) {
                int row = mw * 32 + i * 16 + (lane & 15);
                int col = c * 32 + kk + ((lane >> 4) << 3);
                LDSM4(aP[i], smb + ((row * P_STRIDE + col) << 1));
            }
#pragma unroll
            for (int jg = 0; jg < 2; jg++) {
                uint32_t bH[2][4];
#pragma unroll
                for (int jp = 0; jp < 2; jp++) {
                    int nb = nw * 64 + (jg * 2 + jp) * 16;
                    int row = kk + (lane & 7) + ((lane >> 3) & 1) * 8;
                    int col = nb + ((lane >> 4) & 1) * 8;
                    LDSM4T(bH[jp], sV + ((row * P_STRIDE + col) << 1));
                }
#pragma unroll
                for (int i = 0; i < 2; i++)
#pragma unroll
                    for (int jp = 0; jp < 2; jp++) {
                        MMA2(oacc[i][jg * 4 + jp * 2 + 0], aP[i], bH[jp][0], bH[jp][1]);
                        MMA2(oacc[i][jg * 4 + jp * 2 + 1], aP[i], bH[jp][2], bH[jp][3]);
                    }
            }
        }
        __syncthreads();
        if (c + 2 < 8) { load_v(c & 1, c + 2); CP_COMMIT(); }
    }

#pragma unroll
    for (int i = 0; i < 2; i++)
#pragma unroll
        for (int half = 0; half < 2; half++) {
            int gr = m0 + mw * 32 + i * 16 + half * 8 + lr4;
            __half* ch = awh + (size_t)z * WIN + (size_t)gr * 256;
#pragma unroll
            for (int j = 0; j < 8; j++) {
                int c = nw * 64 + j * 8 + lc2;
                *(__half2*)(ch + c) = __halves2half2(
                    __float2half(oacc[i][j][half * 2 + 0]),
                    __float2half(oacc[i][j][half * 2 + 1]));
            }
        }
}

// ---------------------------------------------------------------------------
// Packing — 3 launches.
// ---------------------------------------------------------------------------
struct WPtrs { const float* w[8]; };

__global__ void packT8_kernel(WPtrs ws, __half* __restrict__ oh) {
    const float* W = ws.w[blockIdx.z];
    __half* o_h = oh + (size_t)blockIdx.z * 65536;
    for (int i = blockIdx.x * 256 + threadIdx.x; i < 65536; i += gridDim.x * 256) {
        int n = i >> 8, k = i & 255;
        o_h[i] = __float2half(W[k * 256 + n]);
    }
}

__global__ void packW2_kernel(const float* __restrict__ w1, const float* __restrict__ w2,
                              __half* __restrict__ o1, __half* __restrict__ o2) {
    const float* W = blockIdx.z ? w2 : w1;
    __half* O = blockIdx.z ? o2 : o1;
    int K = blockIdx.z ? 2048 : 512;
    int N = blockIdx.z ? 256 : 2048;
    size_t total = (size_t)K * N;
    for (size_t i = (size_t)blockIdx.x * blockDim.x + threadIdx.x; i < total;
         i += (size_t)gridDim.x * blockDim.x) {
        size_t n = i / K, k = i % K;
        O[i] = __float2half(W[k * (size_t)N + n]);
    }
}

__global__ void packh2_kernel(const float* __restrict__ x0, const float* __restrict__ x1,
                              __half* __restrict__ y0, __half* __restrict__ y1) {
    const float* x = blockIdx.z ? x1 : x0;
    __half* y = blockIdx.z ? y1 : y0;
    size_t i = ((size_t)blockIdx.x * 256 + threadIdx.x) * 4;
    float4 v = *(const float4*)(x + i);
    *(__half2*)(y + i) = __halves2half2(__float2half(v.x), __float2half(v.y));
    *(__half2*)(y + i + 2) = __halves2half2(__float2half(v.z), __float2half(v.w));
}

// ---------------------------------------------------------------------------
#define SM_GEMM  (2 * (128 * 72 + 256 * 72) * 2)   // 110592 B (big)
#define SM_GEMMS (2 * (128 * 72 + 128 * 72) * 2)   // 73728 B  (small, 2 CTAs/SM)

static bool g_attr = false;
static void set_attrs() {
    if (g_attr) return;
    cudaFuncSetAttribute(mma_gemm_s<4, 1>, cudaFuncAttributeMaxDynamicSharedMemorySize, SM_GEMMS);
    cudaFuncSetAttribute(mma_gemm_s<3, 3>, cudaFuncAttributeMaxDynamicSharedMemorySize, SM_GEMMS);
    cudaFuncSetAttribute(mma_gemm<2, 4>, cudaFuncAttributeMaxDynamicSharedMemorySize, SM_GEMM);
    cudaFuncSetAttribute(mma_gemm<2, 5>, cudaFuncAttributeMaxDynamicSharedMemorySize, SM_GEMM);
    cudaFuncSetAttribute(mma_gemm<0, 6>, cudaFuncAttributeMaxDynamicSharedMemorySize, SM_GEMM);
    cudaFuncSetAttribute(attn_fused, cudaFuncAttributeMaxDynamicSharedMemorySize, ATT_SMEM);
    g_attr = true;
}

extern "C" void kernel_launch(void* const* d_in, const int* in_sizes, int n_in,
                              void* d_out, int out_size)
{
    set_attrs();

    const float* feat0 = (const float*)d_in[0];
    const float* feat1 = (const float*)d_in[1];
    const float* mask  = (const float*)d_in[2];
    const float* i_wq  = (const float*)d_in[6];
    const float* i_wk  = (const float*)d_in[7];
    const float* i_wv  = (const float*)d_in[8];
    const float* i_wfc = (const float*)d_in[9];
    const float* i_g   = (const float*)d_in[10];
    const float* i_b   = (const float*)d_in[11];
    const float* e_wq  = (const float*)d_in[12];
    const float* e_wk  = (const float*)d_in[13];
    const float* e_wv  = (const float*)d_in[14];
    const float* e_wfc = (const float*)d_in[15];
    const float* e_g   = (const float*)d_in[16];
    const float* e_b   = (const float*)d_in[17];
    const float* w1    = (const float*)d_in[18];
    const float* w2    = (const float*)d_in[19];
    const float* fg    = (const float*)d_in[20];
    const float* fb    = (const float*)d_in[21];
    float* out = (float*)d_out;

    __half *in0h, *in1h, *qkv, *awh, *xbh, *ah, *hh, *wTh, *w1h, *w2h;
    float *f0f;
    cudaGetSymbolAddress((void**)&in0h, g_in0h);
    cudaGetSymbolAddress((void**)&in1h, g_in1h);
    cudaGetSymbolAddress((void**)&qkv, g_qkv);
    cudaGetSymbolAddress((void**)&awh, g_awh);
    cudaGetSymbolAddress((void**)&xbh, g_xbh);
    cudaGetSymbolAddress((void**)&ah, g_ah);
    cudaGetSymbolAddress((void**)&hh, g_hh);
    cudaGetSymbolAddress((void**)&wTh, g_wTh);
    cudaGetSymbolAddress((void**)&w1h, g_w1h);
    cudaGetSymbolAddress((void**)&w2h, g_w2h);
    cudaGetSymbolAddress((void**)&f0f, g_f0f);

    const dim3 blk512(512);
    const dim3 blk256(256);
    const dim3 gproj(1, 1024, 1);
    const dim3 gqkv(6, 1024, 1);
    const dim3 gattn(1, 2, 512);
    const dim3 gffn1(16, 1024, 1);

    // ---- packing (3 launches) ----
    WPtrs wp;
    wp.w[0] = i_wq; wp.w[1] = i_wk; wp.w[2] = i_wv; wp.w[3] = i_wfc;
    wp.w[4] = e_wq; wp.w[5] = e_wk; wp.w[6] = e_wv; wp.w[7] = e_wfc;
    packT8_kernel<<<dim3(32, 1, 8), blk256>>>(wp, wTh);
    packW2_kernel<<<dim3(512, 1, 2), blk256>>>(w1, w2, w1h, w2h);
    packh2_kernel<<<dim3(32768, 1, 2), blk256>>>(feat0, feat1, in0h, in1h);

    // ======== Block 1 (intra) ========
    mma_gemm_s<4, 1><<<gqkv, blk256, SM_GEMMS>>>(in0h, in0h, wTh + 0 * 65536,
        qkv, 256, QKV_STRIDE);
    attn_fused<<<gattn, blk512, ATT_SMEM>>>(qkv, awh, mask);
    mma_gemm<2, 4><<<gproj, blk512, SM_GEMM>>>(awh, wTh + 3 * 65536,
        f0f, xbh, feat0, i_g, i_b, 256, 256);

    // ======== Block 2 (inter) ========
    mma_gemm_s<4, 1><<<gqkv, blk256, SM_GEMMS>>>(xbh, in1h, wTh + 4 * 65536,
        qkv, 256, QKV_STRIDE);
    attn_fused<<<gattn, blk512, ATT_SMEM>>>(qkv, awh, mask);
    mma_gemm<2, 5><<<gproj, blk512, SM_GEMM>>>(awh, wTh + 7 * 65536,
        nullptr, ah, nullptr, e_g, e_b, 256, 256);

    // ======== FFN ========
    mma_gemm_s<3, 3><<<gffn1, blk256, SM_GEMMS>>>(xbh, ah, w1h,
        hh, 512, 2048);
    mma_gemm<0, 6><<<gproj, blk512, SM_GEMM>>>(hh, w2h,
        out, nullptr, f0f, fg, fb, 2048, 256);
}